// round 10
// baseline (speedup 1.0000x reference)
#include <cuda_runtime.h>
#include <cuda_fp16.h>
#include <cstdint>
#include <cstddef>

// ---------------------------------------------------------------------------
// MultiDimHiPPO2 on sm_100 (non-'a' PTX target: NO tcgen05; legacy mma.sync).
//
//   out[b, f, m] = base[b, f, m] + sum_k T[f,k] * slice[b,k,m]
//   T[f,k] = cos(2pi*(k+tok)*f/8192)        for f in [0,512)
//          = sin(2pi*(k+tok)*(f-512)/8192)  for f in [512,1024)
//
// fp16 m16n8k16 MMA, f32 accumulate (fp16 mantissa == tf32 mantissa).
// GEMM: CTA 128f x 128m, 256 thr, 2 CTAs/SM, 5-stage cp.async pipeline.
// R10: convoy decorrelation -- warp-parity substep stagger + within-warp
// interleave of LDS / LDGSTS bursts under MMA cover.
// ---------------------------------------------------------------------------

#define KDIM    4096
#define MDIM    1024
#define FDIM    1024
#define NKS     (KDIM / 16)       // 256 k-steps of 16
#define NITER   (NKS / 2)         // 128 stages of 32 k
#define STAGES  5
#define STAGE_A_BYTES 8192        // 128 f x 32 k x 2B (frag order)
#define STAGE_B_BYTES 8192        // 128 m x 32 k x 2B (frag order)
#define STAGE_BYTES   (STAGE_A_BYTES + STAGE_B_BYTES)   // 16 KB
#define SMEM_TOTAL    (STAGES * STAGE_BYTES)            // 80 KB per CTA

// A-frag: AfragH[(rb16*256 + s)*32 + lane] = uint4{a0,a1,a2,a3} (half2 each)
__device__ uint4 AfragH[64 * NKS * 32];                  // 8 MB
// B-frag: BfragH[(((b*256+s)*32 + c)*2 + q)*32 + lane] = uint4{b0A,b1A,b0B,b1B}
__device__ uint4 BfragH[4 * NKS * 32 * 2 * 32];          // 32 MB

__device__ __forceinline__ uint32_t smem_u32(const void* p) {
    uint32_t a;
    asm("{ .reg .u64 t; cvta.to.shared.u64 t, %1; cvt.u32.u64 %0, t; }"
        : "=r"(a) : "l"(p));
    return a;
}

// exact integer phase -> trig value
__device__ __forceinline__ float trigvalf(int k, int tok, int n, bool use_sin) {
    int p = ((k + tok) * n) & 8191;
    if (p >= 4096) p -= 8192;
    float ang = (float)p * (6.28318530718f / 8192.0f);
    return use_sin ? __sinf(ang) : __cosf(ang);
}
__device__ __forceinline__ uint32_t pack_h2(float lo, float hi) {
    __half2 h = __floats2half2_rn(lo, hi);
    return *reinterpret_cast<uint32_t*>(&h);
}

// ---------------- kernel 1: merged pre-pass (unchanged, proven) ----------------
__global__ void __launch_bounds__(256) prep_kernel(const int* __restrict__ tokp,
                                                   const float* __restrict__ slice)
{
    if (blockIdx.x < 2048) {
        int t = blockIdx.x * 256 + threadIdx.x;        // 0 .. 512K-1
        int lane = t & 31;
        int s    = (t >> 5) & 255;
        int rb16 = t >> 13;                            // 0..63
        int g   = lane >> 2;
        int tig = lane & 3;
        int token = tokp ? tokp[0] : 1024;

        int f1 = rb16 * 16 + g;
        int f2 = f1 + 8;
        bool use_sin = (f1 >= 512);
        int n1 = f1 & 511;
        int n2 = f2 & 511;
        int k0 = s * 16 + 2 * tig;

        uint4 v;
        v.x = pack_h2(trigvalf(k0,     token, n1, use_sin), trigvalf(k0 + 1, token, n1, use_sin));
        v.y = pack_h2(trigvalf(k0,     token, n2, use_sin), trigvalf(k0 + 1, token, n2, use_sin));
        v.z = pack_h2(trigvalf(k0 + 8, token, n1, use_sin), trigvalf(k0 + 9, token, n1, use_sin));
        v.w = pack_h2(trigvalf(k0 + 8, token, n2, use_sin), trigvalf(k0 + 9, token, n2, use_sin));
        AfragH[t] = v;
    } else {
        int t = (blockIdx.x - 2048) * 256 + threadIdx.x;  // 0 .. 2M-1
        int lane = t & 31;
        int q    = (t >> 5) & 1;
        int c    = (t >> 6) & 31;
        int s    = (t >> 11) & 255;
        int b    = t >> 19;
        int g   = lane >> 2;
        int tig = lane & 3;

        int k0 = s * 16 + 2 * tig;
        int mA = c * 32 + (2 * q) * 8 + g;
        int mB = mA + 8;

        const float* sp = slice + (size_t)b * KDIM * MDIM;
        const float* r0 = sp + (size_t)k0 * MDIM;
        const float* r1 = sp + (size_t)(k0 + 1) * MDIM;
        const float* r8 = sp + (size_t)(k0 + 8) * MDIM;
        const float* r9 = sp + (size_t)(k0 + 9) * MDIM;

        uint4 v;
        v.x = pack_h2(r0[mA], r1[mA]);
        v.y = pack_h2(r8[mA], r9[mA]);
        v.z = pack_h2(r0[mB], r1[mB]);
        v.w = pack_h2(r8[mB], r9[mB]);
        BfragH[t] = v;
    }
}

// ---------------- kernel 2: the GEMM ----------------
#define MMAH(acc, av, b0, b1)                                                   \
    asm volatile(                                                               \
        "mma.sync.aligned.m16n8k16.row.col.f32.f16.f16.f32 "                    \
        "{%0,%1,%2,%3}, {%4,%5,%6,%7}, {%8,%9}, {%0,%1,%2,%3};\n"               \
        : "+f"((acc)[0]), "+f"((acc)[1]), "+f"((acc)[2]), "+f"((acc)[3])        \
        : "r"((av).x), "r"((av).y), "r"((av).z), "r"((av).w),                   \
          "r"(b0), "r"(b1))

#define CPA16(dst, src)                                                         \
    asm volatile("{ .reg .u64 g; cvta.to.global.u64 g, %1;"                     \
                 "  cp.async.cg.shared.global [%0], [g], 16; }"                 \
                 :: "r"(dst), "l"(src) : "memory")
#define CP_COMMIT() asm volatile("cp.async.commit_group;" ::: "memory")
#define CP_WAIT3()  asm volatile("cp.async.wait_group 3;" ::: "memory")

#define LDS128U(v, addr)                                                        \
    asm volatile("ld.shared.v4.u32 {%0,%1,%2,%3}, [%4];"                        \
                 : "=r"((v).x), "=r"((v).y), "=r"((v).z), "=r"((v).w)           \
                 : "r"(addr))

// issue cp.async copies for pipeline stage i into smem slot (256 threads)
__device__ __forceinline__ void issue_stage(uint32_t sbase, int slot, int i,
                                            int fb, int mb, int b, int tid)
{
    uint32_t sa  = sbase + slot * STAGE_BYTES;
    uint32_t sbB = sa + STAGE_A_BYTES;
    // A: 512 uint4 ([ss:2][rb:8][lane:32]), 2 per thread
    #pragma unroll
    for (int j = 0; j < 2; j++) {
        int c    = tid + 256 * j;
        int ss   = c >> 8;
        int rem  = c & 255;
        int rb   = rem >> 5;
        int lane = c & 31;
        const uint4* src = AfragH + ((size_t)(fb * 8 + rb) * NKS + (2 * i + ss)) * 32 + lane;
        CPA16(sa + c * 16, src);
    }
    // B: 512 uint4 ([ss:2][cl:4][q:2][lane:32]), 2 per thread
    #pragma unroll
    for (int j = 0; j < 2; j++) {
        int c    = tid + 256 * j;
        int ss   = c >> 8;
        int rem  = c & 255;
        int cl   = rem >> 6;
        int q    = (rem >> 5) & 1;
        int lane = c & 31;
        const uint4* src = BfragH +
            (((size_t)(b * NKS + 2 * i + ss) * 32 + (mb * 4 + cl)) * 2 + q) * 32 + lane;
        CPA16(sbB + c * 16, src);
    }
}

__global__ void __launch_bounds__(256, 2) hippo_gemm(
    const float* __restrict__ base,
    float*       __restrict__ out)
{
    extern __shared__ char smem_raw[];
    const uint32_t sbase = smem_u32(smem_raw);

    const int tid  = threadIdx.x;
    const int warp = tid >> 5;
    const int lane = tid & 31;
    const int g    = lane >> 2;
    const int tig  = lane & 3;

    const int mb = blockIdx.x;            // 0..7   (128 m per CTA)
    const int fb = blockIdx.y;            // 0..7   (128 freq per CTA)
    const int b  = blockIdx.z;

    const int warp_f = warp & 1;          // 2 freq halves of 64
    const int warp_n = warp >> 1;         // 4 m-chunks of 32
    const int rbg0 = fb * 8 + warp_f * 4; // first 16-row block of this warp

    // substep stagger: even warps do ss0 first, odd warps ss1 first
    const int sp = warp & 1;              // first substep for this warp
    const int sq = 1 - sp;

    float acc[4][4][4];                   // 64 regs
    #pragma unroll
    for (int rb = 0; rb < 4; rb++)
        #pragma unroll
        for (int j = 0; j < 4; j++)
            #pragma unroll
            for (int c = 0; c < 4; c++) acc[rb][j][c] = 0.f;

    // ---- prologue: fill stages 0..3
    #pragma unroll
    for (int i = 0; i < STAGES - 1; i++) {
        issue_stage(sbase, i, i, fb, mb, b, tid);
        CP_COMMIT();
    }

    // per-warp smem fragment bases (slot-relative)
    const uint32_t a_off = warp_f * 2048 + lane * 16;   // + ss*4096 + rbi*512
    const uint32_t b_off = STAGE_A_BYTES + warp_n * 1024 + lane * 16; // + ss*4096 + q*512

    #pragma unroll 1
    for (int i = 0; i < NITER; i++) {
        CP_WAIT3();            // stage i arrived
        __syncthreads();       // visibility + slot-overwrite protection

        const uint32_t slot_base = sbase + (i % STAGES) * STAGE_BYTES;
        const uint32_t aa_p = slot_base + a_off + sp * 4096;
        const uint32_t ba_p = slot_base + b_off + sp * 4096;
        const uint32_t aa_q = slot_base + a_off + sq * 4096;
        const uint32_t ba_q = slot_base + b_off + sq * 4096;

        uint4 aP[4], bP[2], aQ[4], bQ[2];

        // load frags for this warp's FIRST substep
        #pragma unroll
        for (int rb = 0; rb < 4; rb++) LDS128U(aP[rb], aa_p + rb * 512);
        #pragma unroll
        for (int q = 0; q < 2; q++)    LDS128U(bP[q], ba_p + q * 512);

        // MMA first half of substep p (covers LDS completion of aP/bP for the
        // other-parity warps; crossbar now shared between halves of the CTA)
        #pragma unroll
        for (int rb = 0; rb < 2; rb++) {
            MMAH(acc[rb][0], aP[rb], bP[0].x, bP[0].y);
            MMAH(acc[rb][1], aP[rb], bP[0].z, bP[0].w);
            MMAH(acc[rb][2], aP[rb], bP[1].x, bP[1].y);
            MMAH(acc[rb][3], aP[rb], bP[1].z, bP[1].w);
        }

        // issue next stage's global->smem copies under MMA cover
        if (i + STAGES - 1 < NITER)
            issue_stage(sbase, (i + STAGES - 1) % STAGES, i + STAGES - 1, fb, mb, b, tid);
        CP_COMMIT();

        // load frags for the SECOND substep (under cover of p's remaining MMAs)
        #pragma unroll
        for (int rb = 0; rb < 4; rb++) LDS128U(aQ[rb], aa_q + rb * 512);
        #pragma unroll
        for (int q = 0; q < 2; q++)    LDS128U(bQ[q], ba_q + q * 512);

        // MMA second half of substep p
        #pragma unroll
        for (int rb = 2; rb < 4; rb++) {
            MMAH(acc[rb][0], aP[rb], bP[0].x, bP[0].y);
            MMAH(acc[rb][1], aP[rb], bP[0].z, bP[0].w);
            MMAH(acc[rb][2], aP[rb], bP[1].x, bP[1].y);
            MMAH(acc[rb][3], aP[rb], bP[1].z, bP[1].w);
        }
        // MMA all of substep q
        #pragma unroll
        for (int rb = 0; rb < 4; rb++) {
            MMAH(acc[rb][0], aQ[rb], bQ[0].x, bQ[0].y);
            MMAH(acc[rb][1], aQ[rb], bQ[0].z, bQ[0].w);
            MMAH(acc[rb][2], aQ[rb], bQ[1].x, bQ[1].y);
            MMAH(acc[rb][3], aQ[rb], bQ[1].z, bQ[1].w);
        }
    }

    // ---- epilogue: out = base + acc
    const int col0 = mb * 128 + warp_n * 32 + tig * 2;
    #pragma unroll
    for (int rb = 0; rb < 4; rb++) {
        int r0 = (rbg0 + rb) * 16 + g;
        size_t off0 = ((size_t)(b * FDIM + r0)) * MDIM + col0;
        size_t off1 = off0 + (size_t)8 * MDIM;
        #pragma unroll
        for (int j = 0; j < 4; j++) {
            size_t o0 = off0 + j * 8;
            size_t o1 = off1 + j * 8;
            float2 b0 = *(const float2*)(base + o0);
            float2 b1 = *(const float2*)(base + o1);
            float2 w0, w1;
            w0.x = b0.x + acc[rb][j][0];
            w0.y = b0.y + acc[rb][j][1];
            w1.x = b1.x + acc[rb][j][2];
            w1.y = b1.y + acc[rb][j][3];
            *(float2*)(out + o0) = w0;
            *(float2*)(out + o1) = w1;
        }
    }
}

// ---------------- host launch ----------------
extern "C" void kernel_launch(void* const* d_in, const int* in_sizes, int n_in,
                              void* d_out, int out_size)
{
    const float* base  = nullptr;
    const float* slice = nullptr;
    const int*   tok   = nullptr;
    for (int i = 0; i < n_in; i++) {
        if      (in_sizes[i] == 4 * 4096 * 1024) slice = (const float*)d_in[i];
        else if (in_sizes[i] == 4 * 1024 * 1024) base  = (const float*)d_in[i];
        else                                     tok   = (const int*)d_in[i];
    }
    if (!base  && n_in > 0) base  = (const float*)d_in[0];
    if (!slice && n_in > 1) slice = (const float*)d_in[1];

    static bool attr_set = false;
    if (!attr_set) {
        cudaFuncSetAttribute(hippo_gemm,
                             cudaFuncAttributeMaxDynamicSharedMemorySize, SMEM_TOTAL);
        attr_set = true;
    }

    prep_kernel<<<10240, 256>>>(tok, slice);

    dim3 grid(8, 8, 4);   // m-blocks(128) x f-blocks(128) x batch = 256 CTAs
    hippo_gemm<<<grid, 256, SMEM_TOTAL>>>(base, (float*)d_out);
}

// round 13
// speedup vs baseline: 1.0740x; 1.0740x over previous
#include <cuda_runtime.h>
#include <cuda_fp16.h>
#include <cstdint>
#include <cstddef>

// ---------------------------------------------------------------------------
// MultiDimHiPPO2 on sm_100 (non-'a' PTX target: NO tcgen05; legacy mma.sync).
//
//   out[b, f, m] = base[b, f, m] + sum_k T[f,k] * slice[b,k,m]
//   T[f,k] = cos(2pi*(k+tok)*f/8192)        for f in [0,512)
//          = sin(2pi*(k+tok)*(f-512)/8192)  for f in [512,1024)
//
// fp16 m16n8k16 MMA, f32 accumulate (fp16 mantissa == tf32 mantissa).
// GEMM: CTA 128f x 128m, 256 thr, 2 CTAs/SM.
// R11/R12/R13 candidate: 3 stages x 32KB (64 k/stage) -> HALF the barrier
// intervals of R9; next-stage LDGSTS issued under MMA cover; sequential ss
// substeps keep regs ~110. (Third submit; prior two hit broker failures.)
// ---------------------------------------------------------------------------

#define KDIM    4096
#define MDIM    1024
#define FDIM    1024
#define NKS     (KDIM / 16)       // 256 k-steps of 16
#define NITER   (NKS / 4)         // 64 stages of 64 k
#define STAGES  3
#define STAGE_A_BYTES 16384       // 128 f x 64 k x 2B (frag order)
#define STAGE_B_BYTES 16384       // 128 m x 64 k x 2B (frag order)
#define STAGE_BYTES   (STAGE_A_BYTES + STAGE_B_BYTES)   // 32 KB
#define SMEM_TOTAL    (STAGES * STAGE_BYTES)            // 96 KB per CTA

// A-frag: AfragH[(rb16*256 + s)*32 + lane] = uint4{a0,a1,a2,a3} (half2 each)
__device__ uint4 AfragH[64 * NKS * 32];                  // 8 MB
// B-frag: BfragH[(((b*256+s)*32 + c)*2 + q)*32 + lane] = uint4{b0A,b1A,b0B,b1B}
__device__ uint4 BfragH[4 * NKS * 32 * 2 * 32];          // 32 MB

__device__ __forceinline__ uint32_t smem_u32(const void* p) {
    uint32_t a;
    asm("{ .reg .u64 t; cvta.to.shared.u64 t, %1; cvt.u32.u64 %0, t; }"
        : "=r"(a) : "l"(p));
    return a;
}

// exact integer phase -> trig value
__device__ __forceinline__ float trigvalf(int k, int tok, int n, bool use_sin) {
    int p = ((k + tok) * n) & 8191;
    if (p >= 4096) p -= 8192;
    float ang = (float)p * (6.28318530718f / 8192.0f);
    return use_sin ? __sinf(ang) : __cosf(ang);
}
__device__ __forceinline__ uint32_t pack_h2(float lo, float hi) {
    __half2 h = __floats2half2_rn(lo, hi);
    return *reinterpret_cast<uint32_t*>(&h);
}

// ---------------- kernel 1: merged pre-pass (unchanged, proven) ----------------
__global__ void __launch_bounds__(256) prep_kernel(const int* __restrict__ tokp,
                                                   const float* __restrict__ slice)
{
    if (blockIdx.x < 2048) {
        int t = blockIdx.x * 256 + threadIdx.x;        // 0 .. 512K-1
        int lane = t & 31;
        int s    = (t >> 5) & 255;
        int rb16 = t >> 13;                            // 0..63
        int g   = lane >> 2;
        int tig = lane & 3;
        int token = tokp ? tokp[0] : 1024;

        int f1 = rb16 * 16 + g;
        int f2 = f1 + 8;
        bool use_sin = (f1 >= 512);
        int n1 = f1 & 511;
        int n2 = f2 & 511;
        int k0 = s * 16 + 2 * tig;

        uint4 v;
        v.x = pack_h2(trigvalf(k0,     token, n1, use_sin), trigvalf(k0 + 1, token, n1, use_sin));
        v.y = pack_h2(trigvalf(k0,     token, n2, use_sin), trigvalf(k0 + 1, token, n2, use_sin));
        v.z = pack_h2(trigvalf(k0 + 8, token, n1, use_sin), trigvalf(k0 + 9, token, n1, use_sin));
        v.w = pack_h2(trigvalf(k0 + 8, token, n2, use_sin), trigvalf(k0 + 9, token, n2, use_sin));
        AfragH[t] = v;
    } else {
        int t = (blockIdx.x - 2048) * 256 + threadIdx.x;  // 0 .. 2M-1
        int lane = t & 31;
        int q    = (t >> 5) & 1;
        int c    = (t >> 6) & 31;
        int s    = (t >> 11) & 255;
        int b    = t >> 19;
        int g   = lane >> 2;
        int tig = lane & 3;

        int k0 = s * 16 + 2 * tig;
        int mA = c * 32 + (2 * q) * 8 + g;
        int mB = mA + 8;

        const float* sp = slice + (size_t)b * KDIM * MDIM;
        const float* r0 = sp + (size_t)k0 * MDIM;
        const float* r1 = sp + (size_t)(k0 + 1) * MDIM;
        const float* r8 = sp + (size_t)(k0 + 8) * MDIM;
        const float* r9 = sp + (size_t)(k0 + 9) * MDIM;

        uint4 v;
        v.x = pack_h2(r0[mA], r1[mA]);
        v.y = pack_h2(r8[mA], r9[mA]);
        v.z = pack_h2(r0[mB], r1[mB]);
        v.w = pack_h2(r8[mB], r9[mB]);
        BfragH[t] = v;
    }
}

// ---------------- kernel 2: the GEMM ----------------
#define MMAH(acc, av, b0, b1)                                                   \
    asm volatile(                                                               \
        "mma.sync.aligned.m16n8k16.row.col.f32.f16.f16.f32 "                    \
        "{%0,%1,%2,%3}, {%4,%5,%6,%7}, {%8,%9}, {%0,%1,%2,%3};\n"               \
        : "+f"((acc)[0]), "+f"((acc)[1]), "+f"((acc)[2]), "+f"((acc)[3])        \
        : "r"((av).x), "r"((av).y), "r"((av).z), "r"((av).w),                   \
          "r"(b0), "r"(b1))

#define CPA16(dst, src)                                                         \
    asm volatile("{ .reg .u64 g; cvta.to.global.u64 g, %1;"                     \
                 "  cp.async.cg.shared.global [%0], [g], 16; }"                 \
                 :: "r"(dst), "l"(src) : "memory")
#define CP_COMMIT() asm volatile("cp.async.commit_group;" ::: "memory")
#define CP_WAIT1()  asm volatile("cp.async.wait_group 1;" ::: "memory")

#define LDS128U(v, addr)                                                        \
    asm volatile("ld.shared.v4.u32 {%0,%1,%2,%3}, [%4];"                        \
                 : "=r"((v).x), "=r"((v).y), "=r"((v).z), "=r"((v).w)           \
                 : "r"(addr))

// issue cp.async copies for 64k pipeline stage i into smem slot (256 threads)
__device__ __forceinline__ void issue_stage(uint32_t sbase, int slot, int i,
                                            int fb, int mb, int b, int tid)
{
    uint32_t sa  = sbase + slot * STAGE_BYTES;
    uint32_t sbB = sa + STAGE_A_BYTES;
    // A: 1024 uint4 ([ss:4][rb:8][lane:32]), 4 per thread
    #pragma unroll
    for (int j = 0; j < 4; j++) {
        int c    = tid + 256 * j;
        int ss   = c >> 8;
        int rem  = c & 255;
        int rb   = rem >> 5;
        int lane = c & 31;
        const uint4* src = AfragH + ((size_t)(fb * 8 + rb) * NKS + (4 * i + ss)) * 32 + lane;
        CPA16(sa + c * 16, src);
    }
    // B: 1024 uint4 ([ss:4][cl:4][q:2][lane:32]), 4 per thread
    #pragma unroll
    for (int j = 0; j < 4; j++) {
        int c    = tid + 256 * j;
        int ss   = c >> 8;
        int rem  = c & 255;
        int cl   = rem >> 6;
        int q    = (rem >> 5) & 1;
        int lane = c & 31;
        const uint4* src = BfragH +
            (((size_t)(b * NKS + 4 * i + ss) * 32 + (mb * 4 + cl)) * 2 + q) * 32 + lane;
        CPA16(sbB + c * 16, src);
    }
}

__global__ void __launch_bounds__(256, 2) hippo_gemm(
    const float* __restrict__ base,
    float*       __restrict__ out)
{
    extern __shared__ char smem_raw[];
    const uint32_t sbase = smem_u32(smem_raw);

    const int tid  = threadIdx.x;
    const int warp = tid >> 5;
    const int lane = tid & 31;
    const int g    = lane >> 2;
    const int tig  = lane & 3;

    const int mb = blockIdx.x;            // 0..7   (128 m per CTA)
    const int fb = blockIdx.y;            // 0..7   (128 freq per CTA)
    const int b  = blockIdx.z;

    const int warp_f = warp & 1;          // 2 freq halves of 64
    const int warp_n = warp >> 1;         // 4 m-chunks of 32
    const int rbg0 = fb * 8 + warp_f * 4; // first 16-row block of this warp

    float acc[4][4][4];                   // 64 regs
    #pragma unroll
    for (int rb = 0; rb < 4; rb++)
        #pragma unroll
        for (int j = 0; j < 4; j++)
            #pragma unroll
            for (int c = 0; c < 4; c++) acc[rb][j][c] = 0.f;

    // ---- prologue: fill stages 0 and 1
    issue_stage(sbase, 0, 0, fb, mb, b, tid); CP_COMMIT();
    issue_stage(sbase, 1, 1, fb, mb, b, tid); CP_COMMIT();

    // per-warp smem fragment bases (slot-relative); substep stride = 4096
    const uint32_t a_off = warp_f * 2048 + lane * 16;                 // + ss*4096 + rbi*512
    const uint32_t b_off = STAGE_A_BYTES + warp_n * 1024 + lane * 16; // + ss*4096 + q*512

    #pragma unroll 1
    for (int i = 0; i < NITER; i++) {
        CP_WAIT1();            // stage i arrived (i+1 may be in flight)
        __syncthreads();       // visibility of all threads' copies + slot reuse safety

        const uint32_t slot_base = sbase + (i % STAGES) * STAGE_BYTES;

        // ---- substep 0: load frags, then start next-stage LDGSTS under MMA cover
        uint4 aF[4], bF[2];
        {
            uint32_t aa = slot_base + a_off;
            uint32_t ba = slot_base + b_off;
            #pragma unroll
            for (int rb = 0; rb < 4; rb++) LDS128U(aF[rb], aa + rb * 512);
            #pragma unroll
            for (int q = 0; q < 2; q++)    LDS128U(bF[q], ba + q * 512);
        }

        if (i + 2 < NITER)
            issue_stage(sbase, (i + 2) % STAGES, i + 2, fb, mb, b, tid);
        CP_COMMIT();           // exactly one commit per iteration

        #pragma unroll
        for (int rb = 0; rb < 4; rb++) {
            MMAH(acc[rb][0], aF[rb], bF[0].x, bF[0].y);
            MMAH(acc[rb][1], aF[rb], bF[0].z, bF[0].w);
            MMAH(acc[rb][2], aF[rb], bF[1].x, bF[1].y);
            MMAH(acc[rb][3], aF[rb], bF[1].z, bF[1].w);
        }

        // ---- substeps 1..3: sequential load -> mma
        #pragma unroll
        for (int ss = 1; ss < 4; ss++) {
            uint32_t aa = slot_base + a_off + ss * 4096;
            uint32_t ba = slot_base + b_off + ss * 4096;
            #pragma unroll
            for (int rb = 0; rb < 4; rb++) LDS128U(aF[rb], aa + rb * 512);
            #pragma unroll
            for (int q = 0; q < 2; q++)    LDS128U(bF[q], ba + q * 512);

            #pragma unroll
            for (int rb = 0; rb < 4; rb++) {
                MMAH(acc[rb][0], aF[rb], bF[0].x, bF[0].y);
                MMAH(acc[rb][1], aF[rb], bF[0].z, bF[0].w);
                MMAH(acc[rb][2], aF[rb], bF[1].x, bF[1].y);
                MMAH(acc[rb][3], aF[rb], bF[1].z, bF[1].w);
            }
        }
    }

    // ---- epilogue: out = base + acc
    const int col0 = mb * 128 + warp_n * 32 + tig * 2;
    #pragma unroll
    for (int rb = 0; rb < 4; rb++) {
        int r0 = (rbg0 + rb) * 16 + g;
        size_t off0 = ((size_t)(b * FDIM + r0)) * MDIM + col0;
        size_t off1 = off0 + (size_t)8 * MDIM;
        #pragma unroll
        for (int j = 0; j < 4; j++) {
            size_t o0 = off0 + j * 8;
            size_t o1 = off1 + j * 8;
            float2 b0 = *(const float2*)(base + o0);
            float2 b1 = *(const float2*)(base + o1);
            float2 w0, w1;
            w0.x = b0.x + acc[rb][j][0];
            w0.y = b0.y + acc[rb][j][1];
            w1.x = b1.x + acc[rb][j][2];
            w1.y = b1.y + acc[rb][j][3];
            *(float2*)(out + o0) = w0;
            *(float2*)(out + o1) = w1;
        }
    }
}

// ---------------- host launch ----------------
extern "C" void kernel_launch(void* const* d_in, const int* in_sizes, int n_in,
                              void* d_out, int out_size)
{
    const float* base  = nullptr;
    const float* slice = nullptr;
    const int*   tok   = nullptr;
    for (int i = 0; i < n_in; i++) {
        if      (in_sizes[i] == 4 * 4096 * 1024) slice = (const float*)d_in[i];
        else if (in_sizes[i] == 4 * 1024 * 1024) base  = (const float*)d_in[i];
        else                                     tok   = (const int*)d_in[i];
    }
    if (!base  && n_in > 0) base  = (const float*)d_in[0];
    if (!slice && n_in > 1) slice = (const float*)d_in[1];

    static bool attr_set = false;
    if (!attr_set) {
        cudaFuncSetAttribute(hippo_gemm,
                             cudaFuncAttributeMaxDynamicSharedMemorySize, SMEM_TOTAL);
        attr_set = true;
    }

    prep_kernel<<<10240, 256>>>(tok, slice);

    dim3 grid(8, 8, 4);   // m-blocks(128) x f-blocks(128) x batch = 256 CTAs
    hippo_gemm<<<grid, 256, SMEM_TOTAL>>>(base, (float*)d_out);
}